// round 13
// baseline (speedup 1.0000x reference)
#include <cuda_runtime.h>
#include <cuda_fp16.h>
#include <math.h>
#include <stdint.h>

#define VOCAB 32000
#define EMB 32
#define REC 16
#define SEQ 256
#define BATCH 32
#define NROWS (SEQ*BATCH)      // 8192
#define LOG2E 1.4426950408889634f
#define LN2   0.6931471805599453f

#define MCH 512                // rows per CTA chunk
#define NT 32                  // m-tiles per CTA (MCH/16)
#define GY (NROWS/MCH)         // 16
#define GX (VOCAB/128)         // 250 (8 warps * 16 vocab)
#define ASTRIDE 48             // bytes per smem A row

// ---- scratch ----
__device__ __half g_h16[NROWS*REC];     // hidden fp16, [row][e]
__device__ __half g_V16[VOCAB*REC];     // V*log2e fp16, [v][e]
__device__ float  g_ih[BATCH*SEQ*REC];
__device__ float  g_sums[NROWS];
__device__ float  g_m[NROWS];           // lse (nat)

// ---- helpers ----
__device__ __forceinline__ uint32_t su32(const void* p) {
    uint32_t a;
    asm("{ .reg .u64 t; cvta.to.shared.u64 t, %1; cvt.u32.u64 %0, t; }" : "=r"(a) : "l"(p));
    return a;
}
__device__ __forceinline__ float ex2f(float x) {
    float y; asm("ex2.approx.f32 %0, %1;" : "=f"(y) : "f"(x)); return y;
}
__device__ __forceinline__ float rcpf(float x) {
    float y; asm("rcp.approx.f32 %0, %1;" : "=f"(y) : "f"(x)); return y;
}
__device__ __forceinline__ __half2 h2ex2(__half2 x) {
    uint32_t xi = *(uint32_t*)&x, yi;
    asm("ex2.approx.f16x2 %0, %1;" : "=r"(yi) : "r"(xi));
    return *(__half2*)&yi;
}
__device__ __forceinline__ void ldsmx4(uint32_t a[4], uint32_t addr) {
    asm volatile("ldmatrix.sync.aligned.m8n8.x4.shared.b16 {%0,%1,%2,%3}, [%4];"
        : "=r"(a[0]), "=r"(a[1]), "=r"(a[2]), "=r"(a[3]) : "r"(addr));
}
__device__ __forceinline__ void mma16(float c[4], const uint32_t a[4], uint32_t b0, uint32_t b1) {
    asm volatile("mma.sync.aligned.m16n8k16.row.col.f32.f16.f16.f32 "
        "{%0,%1,%2,%3},{%4,%5,%6,%7},{%8,%9},{%0,%1,%2,%3};"
        : "+f"(c[0]), "+f"(c[1]), "+f"(c[2]), "+f"(c[3])
        : "r"(a[0]), "r"(a[1]), "r"(a[2]), "r"(a[3]), "r"(b0), "r"(b1));
}

// ---- small kernels ----
__global__ void k_zero() { g_sums[blockIdx.x * blockDim.x + threadIdx.x] = 0.f; }

__global__ void k_prepV(const float* __restrict__ V) {
    int v = blockIdx.x * 128 + threadIdx.x;
    const float4* s = (const float4*)(V + (size_t)v * REC);
    __half2 o[8];
#pragma unroll
    for (int q = 0; q < 4; q++) {
        float4 f = s[q];
        o[2*q]   = __floats2half2_rn(f.x * LOG2E, f.y * LOG2E);
        o[2*q+1] = __floats2half2_rn(f.z * LOG2E, f.w * LOG2E);
    }
    uint4* d = (uint4*)g_V16 + (size_t)v * 2;
    d[0] = *(uint4*)&o[0];
    d[1] = *(uint4*)&o[4];
}

__global__ void k_ih(const int* __restrict__ idx, const float* __restrict__ emb,
                     const float* __restrict__ U, const float* __restrict__ b1,
                     const float* __restrict__ b2) {
    int i = blockIdx.x * blockDim.x + threadIdx.x;
    int row = i >> 4, j = i & 15;
    int t = row >> 5, b = row & 31;
    int tok = idx[row];
    const float4* x4 = (const float4*)(emb + (size_t)tok * EMB);
    const float4* u4 = (const float4*)(U + j * EMB);
    float acc = b1[j] + b2[j];
#pragma unroll
    for (int q = 0; q < 8; q++) {
        float4 x = x4[q], u = u4[q];
        acc = fmaf(x.x, u.x, acc); acc = fmaf(x.y, u.y, acc);
        acc = fmaf(x.z, u.z, acc); acc = fmaf(x.w, u.w, acc);
    }
    g_ih[b * (SEQ * REC) + t * REC + j] = acc * (2.0f * LOG2E);
}

// recurrence: 16 CTAs x 1 warp; lane owns h[j]; 2 batches per warp (width-16 shfl)
__global__ void k_rnn(const float* __restrict__ W, const float* __restrict__ h0) {
    __shared__ float ihs[2][SEQ * REC];   // 32 KB
    int lane = threadIdx.x;
    int sub = lane >> 4;                  // 0/1
    int j   = lane & 15;
    int b   = 2 * blockIdx.x + sub;

    for (int i = j; i < SEQ * REC; i += 16)
        ihs[sub][i] = g_ih[b * (SEQ * REC) + i];

    float Wp[16];
#pragma unroll
    for (int r = 0; r < 16; r++) Wp[r] = W[j * REC + ((j + r) & 15)];

    float h = h0[j];
    __syncwarp();

    __half* hdst = &g_h16[b * REC + j];
    const float* ihp = &ihs[sub][j];
    for (int t = 0; t < SEQ; t++) {
        *hdst = __float2half_rn(h);
        if (t == SEQ - 1) break;
        hdst += BATCH * REC;

        float ihv = ihp[t * REC];
        float acc0 = 0.f, acc1 = 0.f;
#pragma unroll
        for (int r = 0; r < 16; r += 2) {
            float ha = __shfl_sync(0xffffffffu, h, (lane + r) & 15, 16);
            float hb = __shfl_sync(0xffffffffu, h, (lane + r + 1) & 15, 16);
            acc0 = fmaf(Wp[r],   ha, acc0);
            acc1 = fmaf(Wp[r+1], hb, acc1);
        }
        float z = fmaf(acc0 + acc1, 2.0f * LOG2E, ihv);  // 2*log2e*(ih+acc)
        float e = ex2f(z);
        h = fmaf(-2.0f, rcpf(1.0f + e), 1.0f);           // tanh
    }
}

__global__ void k_lse() {
    int i = blockIdx.x * blockDim.x + threadIdx.x;
    g_m[i] = log2f(g_sums[i]) * LN2;
}

// ---- HMMA pass kernels ----
__device__ __forceinline__ void load_bfrag(uint32_t B[2][2], int w0, int lane) {
    int n = lane >> 2, q = lane & 3;
#pragma unroll
    for (int t = 0; t < 2; t++) {
        int v = w0 + (n >> 1) * 4 + (n & 1) + t * 2;
        const uint32_t* vp = (const uint32_t*)&g_V16[(size_t)v * REC];
        B[t][0] = vp[q];
        B[t][1] = vp[q + 4];
    }
}

__global__ void __launch_bounds__(256) k_p1() {
    __shared__ __align__(16) char smA[MCH * ASTRIDE];
    __shared__ float ssum[MCH];
    int tid = threadIdx.x, wid = tid >> 5, lane = tid & 31;
    int mbase = blockIdx.y * MCH;
    int w0 = blockIdx.x * 128 + wid * 16;

    for (int r = tid; r < MCH; r += 256) {
        const uint4* s = (const uint4*)&g_h16[(size_t)(mbase + r) * REC];
        uint4 x0 = s[0], x1 = s[1];
        *(uint4*)(smA + r * ASTRIDE)      = x0;
        *(uint4*)(smA + r * ASTRIDE + 16) = x1;
    }
    for (int r = tid; r < MCH; r += 256) ssum[r] = 0.f;

    uint32_t B[2][2];
    load_bfrag(B, w0, lane);

    uint32_t abase = su32(smA) + (lane & 15) * ASTRIDE + (lane >> 4) * 16;
    __syncthreads();

    int q = lane & 3, g = lane >> 2;
    for (int i = 0; i < NT; i++) {
        int mt = (i + wid * 4) & (NT - 1);
        uint32_t a[4];
        ldsmx4(a, abase + mt * (16 * ASTRIDE));
        float c[4] = {0,0,0,0}, d[4] = {0,0,0,0};
        mma16(c, a, B[0][0], B[0][1]);
        mma16(d, a, B[1][0], B[1][1]);
        // fp16x2 exp: 4 MUFU ops instead of 8
        __half2 clo = h2ex2(__floats2half2_rn(c[0], c[1]));
        __half2 dlo = h2ex2(__floats2half2_rn(d[0], d[1]));
        __half2 chi = h2ex2(__floats2half2_rn(c[2], c[3]));
        __half2 dhi = h2ex2(__floats2half2_rn(d[2], d[3]));
        float2 flo = __half22float2(__hadd2(clo, dlo));
        float2 fhi = __half22float2(__hadd2(chi, dhi));
        float lo = flo.x + flo.y;
        float hi = fhi.x + fhi.y;
        lo += __shfl_xor_sync(0xffffffffu, lo, 1);
        lo += __shfl_xor_sync(0xffffffffu, lo, 2);
        hi += __shfl_xor_sync(0xffffffffu, hi, 1);
        hi += __shfl_xor_sync(0xffffffffu, hi, 2);
        if (q == 0) {
            atomicAdd(&ssum[mt * 16 + g], lo);
            atomicAdd(&ssum[mt * 16 + g + 8], hi);
        }
    }
    __syncthreads();
    for (int r = tid; r < MCH; r += 256) atomicAdd(&g_sums[mbase + r], ssum[r]);
}

__global__ void __launch_bounds__(256) k_p2(float* __restrict__ out) {
    __shared__ __align__(16) char smA[MCH * ASTRIDE];
    __shared__ float ms[MCH];
    int tid = threadIdx.x, wid = tid >> 5, lane = tid & 31;
    int mbase = blockIdx.y * MCH;
    int w0 = blockIdx.x * 128 + wid * 16;

    for (int r = tid; r < MCH; r += 256) {
        const uint4* s = (const uint4*)&g_h16[(size_t)(mbase + r) * REC];
        uint4 x0 = s[0], x1 = s[1];
        *(uint4*)(smA + r * ASTRIDE)      = x0;
        *(uint4*)(smA + r * ASTRIDE + 16) = x1;
    }
    for (int r = tid; r < MCH; r += 256) ms[r] = g_m[mbase + r];

    uint32_t B[2][2];
    load_bfrag(B, w0, lane);

    uint32_t abase = su32(smA) + (lane & 15) * ASTRIDE + (lane >> 4) * 16;
    __syncthreads();

    int q = lane & 3, g = lane >> 2;
    int vcol = w0 + 4 * q;
    for (int i = 0; i < NT; i++) {
        int mt = (i + wid * 4) & (NT - 1);
        uint32_t a[4];
        ldsmx4(a, abase + mt * (16 * ASTRIDE));
        float c[4] = {0,0,0,0}, d[4] = {0,0,0,0};
        mma16(c, a, B[0][0], B[0][1]);
        mma16(d, a, B[1][0], B[1][1]);
        int r0 = mt * 16 + g;
        float m0 = ms[r0], m1 = ms[r0 + 8];
        float4 o0, o1;
        o0.x = fmaf(c[0], LN2, -m0); o0.y = fmaf(c[1], LN2, -m0);
        o0.z = fmaf(d[0], LN2, -m0); o0.w = fmaf(d[1], LN2, -m0);
        o1.x = fmaf(c[2], LN2, -m1); o1.y = fmaf(c[3], LN2, -m1);
        o1.z = fmaf(d[2], LN2, -m1); o1.w = fmaf(d[3], LN2, -m1);
        *(float4*)(out + (size_t)(mbase + r0) * VOCAB + vcol)     = o0;
        *(float4*)(out + (size_t)(mbase + r0 + 8) * VOCAB + vcol) = o1;
    }
}

extern "C" void kernel_launch(void* const* d_in, const int* in_sizes, int n_in,
                              void* d_out, int out_size) {
    const int*   input_batch = (const int*)  d_in[0];
    const float* embedding   = (const float*)d_in[1];
    const float* U           = (const float*)d_in[2];
    const float* W           = (const float*)d_in[3];
    const float* V           = (const float*)d_in[4];
    const float* b1          = (const float*)d_in[5];
    const float* b2          = (const float*)d_in[6];
    const float* h0          = (const float*)d_in[7];
    float* out = (float*)d_out;

    k_zero <<<NROWS / 256, 256>>>();
    k_prepV<<<VOCAB / 128, 128>>>(V);
    k_ih   <<<(NROWS * REC) / 256, 256>>>(input_batch, embedding, U, b1, b2);
    k_rnn  <<<BATCH / 2, 32>>>(W, h0);
    k_p1   <<<dim3(GX, GY), 256>>>();
    k_lse  <<<NROWS / 256, 256>>>();
    k_p2   <<<dim3(GX, GY), 256>>>(out);
}

// round 15
// speedup vs baseline: 1.0806x; 1.0806x over previous
#include <cuda_runtime.h>
#include <cuda_fp16.h>
#include <math.h>
#include <stdint.h>

#define VOCAB 32000
#define EMB 32
#define REC 16
#define SEQ 256
#define BATCH 32
#define NROWS (SEQ*BATCH)      // 8192
#define LOG2E 1.4426950408889634f
#define LN2   0.6931471805599453f

#define MCH 512                // rows per CTA chunk
#define NT 32                  // m-tiles per CTA (MCH/16)
#define GY (NROWS/MCH)         // 16
#define GX (VOCAB/128)         // 250 (8 warps * 16 vocab)
#define ASTRIDE 48             // bytes per smem A row

// ---- scratch ----
__device__ __half g_h16[NROWS*REC];     // hidden fp16, [row][e]
__device__ __half g_V16[VOCAB*REC];     // V*log2e fp16, [v][e]
__device__ float  g_ih[BATCH*SEQ*REC];
__device__ float  g_sums[NROWS];
__device__ float  g_m[NROWS];           // lse (nat)

// ---- helpers ----
__device__ __forceinline__ uint32_t su32(const void* p) {
    uint32_t a;
    asm("{ .reg .u64 t; cvta.to.shared.u64 t, %1; cvt.u32.u64 %0, t; }" : "=r"(a) : "l"(p));
    return a;
}
__device__ __forceinline__ float ex2f(float x) {
    float y; asm("ex2.approx.f32 %0, %1;" : "=f"(y) : "f"(x)); return y;
}
__device__ __forceinline__ float rcpf(float x) {
    float y; asm("rcp.approx.f32 %0, %1;" : "=f"(y) : "f"(x)); return y;
}
__device__ __forceinline__ __half2 h2ex2(__half2 x) {
    uint32_t xi = *(uint32_t*)&x, yi;
    asm("ex2.approx.f16x2 %0, %1;" : "=r"(yi) : "r"(xi));
    return *(__half2*)&yi;
}
__device__ __forceinline__ void ldsmx4(uint32_t a[4], uint32_t addr) {
    asm volatile("ldmatrix.sync.aligned.m8n8.x4.shared.b16 {%0,%1,%2,%3}, [%4];"
        : "=r"(a[0]), "=r"(a[1]), "=r"(a[2]), "=r"(a[3]) : "r"(addr));
}
__device__ __forceinline__ void mma16(float c[4], const uint32_t a[4], uint32_t b0, uint32_t b1) {
    asm volatile("mma.sync.aligned.m16n8k16.row.col.f32.f16.f16.f32 "
        "{%0,%1,%2,%3},{%4,%5,%6,%7},{%8,%9},{%0,%1,%2,%3};"
        : "+f"(c[0]), "+f"(c[1]), "+f"(c[2]), "+f"(c[3])
        : "r"(a[0]), "r"(a[1]), "r"(a[2]), "r"(a[3]), "r"(b0), "r"(b1));
}

// ---- small kernels ----
__global__ void k_zero() { g_sums[blockIdx.x * blockDim.x + threadIdx.x] = 0.f; }

__global__ void k_prepV(const float* __restrict__ V) {
    int v = blockIdx.x * 128 + threadIdx.x;
    const float4* s = (const float4*)(V + (size_t)v * REC);
    __half2 o[8];
#pragma unroll
    for (int q = 0; q < 4; q++) {
        float4 f = s[q];
        o[2*q]   = __floats2half2_rn(f.x * LOG2E, f.y * LOG2E);
        o[2*q+1] = __floats2half2_rn(f.z * LOG2E, f.w * LOG2E);
    }
    uint4* d = (uint4*)g_V16 + (size_t)v * 2;
    d[0] = *(uint4*)&o[0];
    d[1] = *(uint4*)&o[4];
}

__global__ void k_ih(const int* __restrict__ idx, const float* __restrict__ emb,
                     const float* __restrict__ U, const float* __restrict__ b1,
                     const float* __restrict__ b2) {
    int i = blockIdx.x * blockDim.x + threadIdx.x;
    int row = i >> 4, j = i & 15;
    int t = row >> 5, b = row & 31;
    int tok = idx[row];
    const float4* x4 = (const float4*)(emb + (size_t)tok * EMB);
    const float4* u4 = (const float4*)(U + j * EMB);
    float acc = b1[j] + b2[j];
#pragma unroll
    for (int q = 0; q < 8; q++) {
        float4 x = x4[q], u = u4[q];
        acc = fmaf(x.x, u.x, acc); acc = fmaf(x.y, u.y, acc);
        acc = fmaf(x.z, u.z, acc); acc = fmaf(x.w, u.w, acc);
    }
    g_ih[b * (SEQ * REC) + t * REC + j] = acc * (2.0f * LOG2E);
}

// recurrence (R11 version): 1 warp per batch, 2 lanes per unit, double-buffered smem h
__global__ void k_rnn(const float* __restrict__ W, const float* __restrict__ h0) {
    __shared__ float ihs[SEQ * REC];
    __shared__ float hsm[2][REC];
    int b = blockIdx.x, lane = threadIdx.x;

#pragma unroll 8
    for (int i = lane; i < SEQ * REC; i += 32)
        ihs[i] = g_ih[b * (SEQ * REC) + i];

    int j = lane >> 1, half = lane & 1;
    float Wr[8];
#pragma unroll
    for (int k = 0; k < 8; k++) Wr[k] = W[j * REC + half * 8 + k];

    if (lane < REC) hsm[0][lane] = h0[lane];
    __syncwarp();

    int cur = 0;
    __half* hrow = &g_h16[b * REC];
    for (int t = 0; t < SEQ; t++) {
        if (!half) hrow[j] = __float2half_rn(hsm[cur][j]);
        if (t == SEQ - 1) break;
        hrow += BATCH * REC;

        const float* hp = &hsm[cur][half * 8];
        float a0 = Wr[0]*hp[0], a1 = Wr[1]*hp[1];
        a0 = fmaf(Wr[2], hp[2], a0); a1 = fmaf(Wr[3], hp[3], a1);
        a0 = fmaf(Wr[4], hp[4], a0); a1 = fmaf(Wr[5], hp[5], a1);
        a0 = fmaf(Wr[6], hp[6], a0); a1 = fmaf(Wr[7], hp[7], a1);
        float acc = a0 + a1;
        acc += __shfl_xor_sync(0xffffffffu, acc, 1);
        float z = fmaf(acc, 2.0f * LOG2E, ihs[t * REC + j]);
        float e = ex2f(z);
        float hn = fmaf(-2.0f, rcpf(1.0f + e), 1.0f);
        if (!half) hsm[cur ^ 1][j] = hn;
        __syncwarp();
        cur ^= 1;
    }
}

__global__ void k_lse() {
    int i = blockIdx.x * blockDim.x + threadIdx.x;
    g_m[i] = log2f(g_sums[i]) * LN2;
}

// ---- HMMA pass kernels ----
__device__ __forceinline__ void load_bfrag(uint32_t B[2][2], int w0, int lane) {
    int n = lane >> 2, q = lane & 3;
#pragma unroll
    for (int t = 0; t < 2; t++) {
        int v = w0 + (n >> 1) * 4 + (n & 1) + t * 2;
        const uint32_t* vp = (const uint32_t*)&g_V16[(size_t)v * REC];
        B[t][0] = vp[q];
        B[t][1] = vp[q + 4];
    }
}

__global__ void __launch_bounds__(256) k_p1() {
    __shared__ __align__(16) char smA[MCH * ASTRIDE];
    __shared__ float ssum[MCH];
    int tid = threadIdx.x, wid = tid >> 5, lane = tid & 31;
    int mbase = blockIdx.y * MCH;
    int w0 = blockIdx.x * 128 + wid * 16;

    for (int r = tid; r < MCH; r += 256) {
        const uint4* s = (const uint4*)&g_h16[(size_t)(mbase + r) * REC];
        uint4 x0 = s[0], x1 = s[1];
        *(uint4*)(smA + r * ASTRIDE)      = x0;
        *(uint4*)(smA + r * ASTRIDE + 16) = x1;
    }
    for (int r = tid; r < MCH; r += 256) ssum[r] = 0.f;

    uint32_t B[2][2];
    load_bfrag(B, w0, lane);

    uint32_t abase = su32(smA) + (lane & 15) * ASTRIDE + (lane >> 4) * 16;
    __syncthreads();

    int q = lane & 3, g = lane >> 2;
    for (int i = 0; i < NT; i++) {
        int mt = (i + wid * 4) & (NT - 1);
        uint32_t a[4];
        ldsmx4(a, abase + mt * (16 * ASTRIDE));
        float c[4] = {0,0,0,0}, d[4] = {0,0,0,0};
        mma16(c, a, B[0][0], B[0][1]);
        mma16(d, a, B[1][0], B[1][1]);
        __half2 clo = h2ex2(__floats2half2_rn(c[0], c[1]));
        __half2 dlo = h2ex2(__floats2half2_rn(d[0], d[1]));
        __half2 chi = h2ex2(__floats2half2_rn(c[2], c[3]));
        __half2 dhi = h2ex2(__floats2half2_rn(d[2], d[3]));
        float2 flo = __half22float2(__hadd2(clo, dlo));
        float2 fhi = __half22float2(__hadd2(chi, dhi));
        float lo = flo.x + flo.y;
        float hi = fhi.x + fhi.y;
        lo += __shfl_xor_sync(0xffffffffu, lo, 1);
        lo += __shfl_xor_sync(0xffffffffu, lo, 2);
        hi += __shfl_xor_sync(0xffffffffu, hi, 1);
        hi += __shfl_xor_sync(0xffffffffu, hi, 2);
        if (q == 0) {
            atomicAdd(&ssum[mt * 16 + g], lo);
            atomicAdd(&ssum[mt * 16 + g + 8], hi);
        }
    }
    __syncthreads();
    for (int r = tid; r < MCH; r += 256) atomicAdd(&g_sums[mbase + r], ssum[r]);
}

__global__ void __launch_bounds__(256) k_p2(float* __restrict__ out) {
    __shared__ __align__(16) char smA[MCH * ASTRIDE];
    __shared__ float ms[MCH];
    int tid = threadIdx.x, wid = tid >> 5, lane = tid & 31;
    int mbase = blockIdx.y * MCH;
    int w0 = blockIdx.x * 128 + wid * 16;

    for (int r = tid; r < MCH; r += 256) {
        const uint4* s = (const uint4*)&g_h16[(size_t)(mbase + r) * REC];
        uint4 x0 = s[0], x1 = s[1];
        *(uint4*)(smA + r * ASTRIDE)      = x0;
        *(uint4*)(smA + r * ASTRIDE + 16) = x1;
    }
    for (int r = tid; r < MCH; r += 256) ms[r] = g_m[mbase + r];

    uint32_t B[2][2];
    load_bfrag(B, w0, lane);

    uint32_t abase = su32(smA) + (lane & 15) * ASTRIDE + (lane >> 4) * 16;
    __syncthreads();

    int q = lane & 3, g = lane >> 2;
    int vcol = w0 + 4 * q;
    for (int i = 0; i < NT; i++) {
        int mt = (i + wid * 4) & (NT - 1);
        uint32_t a[4];
        ldsmx4(a, abase + mt * (16 * ASTRIDE));
        float c[4] = {0,0,0,0}, d[4] = {0,0,0,0};
        mma16(c, a, B[0][0], B[0][1]);
        mma16(d, a, B[1][0], B[1][1]);
        int r0 = mt * 16 + g;
        float m0 = ms[r0], m1 = ms[r0 + 8];
        float4 o0, o1;
        o0.x = fmaf(c[0], LN2, -m0); o0.y = fmaf(c[1], LN2, -m0);
        o0.z = fmaf(d[0], LN2, -m0); o0.w = fmaf(d[1], LN2, -m0);
        o1.x = fmaf(c[2], LN2, -m1); o1.y = fmaf(c[3], LN2, -m1);
        o1.z = fmaf(d[2], LN2, -m1); o1.w = fmaf(d[3], LN2, -m1);
        *(float4*)(out + (size_t)(mbase + r0) * VOCAB + vcol)     = o0;
        *(float4*)(out + (size_t)(mbase + r0 + 8) * VOCAB + vcol) = o1;
    }
}

extern "C" void kernel_launch(void* const* d_in, const int* in_sizes, int n_in,
                              void* d_out, int out_size) {
    const int*   input_batch = (const int*)  d_in[0];
    const float* embedding   = (const float*)d_in[1];
    const float* U           = (const float*)d_in[2];
    const float* W           = (const float*)d_in[3];
    const float* V           = (const float*)d_in[4];
    const float* b1          = (const float*)d_in[5];
    const float* b2          = (const float*)d_in[6];
    const float* h0          = (const float*)d_in[7];
    float* out = (float*)d_out;

    k_zero <<<NROWS / 256, 256>>>();
    k_prepV<<<VOCAB / 128, 128>>>(V);
    k_ih   <<<(NROWS * REC) / 256, 256>>>(input_batch, embedding, U, b1, b2);
    k_rnn  <<<BATCH, 32>>>(W, h0);
    k_p1   <<<dim3(GX, GY), 256>>>();
    k_lse  <<<NROWS / 256, 256>>>();
    k_p2   <<<dim3(GX, GY), 256>>>(out);
}

// round 16
// speedup vs baseline: 1.1346x; 1.0499x over previous
#include <cuda_runtime.h>
#include <cuda_fp16.h>
#include <math.h>
#include <stdint.h>

#define VOCAB 32000
#define EMB 32
#define REC 16
#define SEQ 256
#define BATCH 32
#define NROWS (SEQ*BATCH)      // 8192
#define LOG2E 1.4426950408889634f
#define LN2   0.6931471805599453f

#define MCH 512                // rows per CTA chunk
#define NT 32                  // m-tiles per CTA
#define GY (NROWS/MCH)         // 16
#define GX (VOCAB/128)         // 250
#define ASTRIDE 48             // bytes per smem A row

// ---- scratch ----
__device__ __half g_h16[NROWS*REC];     // hidden fp16, [row][e]
__device__ float  g_ih[BATCH*SEQ*REC];
__device__ float  g_sums[NROWS];

// ---- helpers ----
__device__ __forceinline__ uint32_t su32(const void* p) {
    uint32_t a;
    asm("{ .reg .u64 t; cvta.to.shared.u64 t, %1; cvt.u32.u64 %0, t; }" : "=r"(a) : "l"(p));
    return a;
}
__device__ __forceinline__ float ex2f(float x) {
    float y; asm("ex2.approx.f32 %0, %1;" : "=f"(y) : "f"(x)); return y;
}
__device__ __forceinline__ float rcpf(float x) {
    float y; asm("rcp.approx.f32 %0, %1;" : "=f"(y) : "f"(x)); return y;
}
__device__ __forceinline__ float lg2f(float x) {
    float y; asm("lg2.approx.f32 %0, %1;" : "=f"(y) : "f"(x)); return y;
}
__device__ __forceinline__ __half2 h2ex2(__half2 x) {
    uint32_t xi = *(uint32_t*)&x, yi;
    asm("ex2.approx.f16x2 %0, %1;" : "=r"(yi) : "r"(xi));
    return *(__half2*)&yi;
}
__device__ __forceinline__ void ldsmx4(uint32_t a[4], uint32_t addr) {
    asm volatile("ldmatrix.sync.aligned.m8n8.x4.shared.b16 {%0,%1,%2,%3}, [%4];"
        : "=r"(a[0]), "=r"(a[1]), "=r"(a[2]), "=r"(a[3]) : "r"(addr));
}
__device__ __forceinline__ void mma16f(float c[4], const uint32_t a[4], uint32_t b0, uint32_t b1) {
    asm volatile("mma.sync.aligned.m16n8k16.row.col.f32.f16.f16.f32 "
        "{%0,%1,%2,%3},{%4,%5,%6,%7},{%8,%9},{%0,%1,%2,%3};"
        : "+f"(c[0]), "+f"(c[1]), "+f"(c[2]), "+f"(c[3])
        : "r"(a[0]), "r"(a[1]), "r"(a[2]), "r"(a[3]), "r"(b0), "r"(b1));
}
__device__ __forceinline__ void mma16h(uint32_t c[2], const uint32_t a[4], uint32_t b0, uint32_t b1) {
    asm volatile("mma.sync.aligned.m16n8k16.row.col.f16.f16.f16.f16 "
        "{%0,%1},{%2,%3,%4,%5},{%6,%7},{%0,%1};"
        : "+r"(c[0]), "+r"(c[1])
        : "r"(a[0]), "r"(a[1]), "r"(a[2]), "r"(a[3]), "r"(b0), "r"(b1));
}

// B fragment straight from f32 V, scaled by log2e (vocab-interleaved perm)
__device__ __forceinline__ void load_bfrag(uint32_t B[2][2], const float* __restrict__ V,
                                           int w0, int lane) {
    int n = lane >> 2, q = lane & 3;
#pragma unroll
    for (int t = 0; t < 2; t++) {
        int v = w0 + (n >> 1) * 4 + (n & 1) + t * 2;
        const float* vp = V + (size_t)v * REC;
        float2 lo = *(const float2*)(vp + 2 * q);
        float2 hi = *(const float2*)(vp + 2 * q + 8);
        __half2 h0 = __floats2half2_rn(lo.x * LOG2E, lo.y * LOG2E);
        __half2 h1 = __floats2half2_rn(hi.x * LOG2E, hi.y * LOG2E);
        B[t][0] = *(uint32_t*)&h0;
        B[t][1] = *(uint32_t*)&h1;
    }
}

// ---- fused prologue: zero sums + ih ----
__global__ void k_ih(const int* __restrict__ idx, const float* __restrict__ emb,
                     const float* __restrict__ U, const float* __restrict__ b1,
                     const float* __restrict__ b2) {
    int i = blockIdx.x * blockDim.x + threadIdx.x;
    if (i < NROWS) g_sums[i] = 0.f;
    int row = i >> 4, j = i & 15;
    int t = row >> 5, b = row & 31;
    int tok = idx[row];
    const float4* x4 = (const float4*)(emb + (size_t)tok * EMB);
    const float4* u4 = (const float4*)(U + j * EMB);
    float acc = b1[j] + b2[j];
#pragma unroll
    for (int q = 0; q < 8; q++) {
        float4 x = x4[q], u = u4[q];
        acc = fmaf(x.x, u.x, acc); acc = fmaf(x.y, u.y, acc);
        acc = fmaf(x.z, u.z, acc); acc = fmaf(x.w, u.w, acc);
    }
    g_ih[b * (SEQ * REC) + t * REC + j] = acc * (2.0f * LOG2E);
}

// recurrence: 1 warp per batch, 2 lanes per unit, double-buffered smem h
__global__ void k_rnn(const float* __restrict__ W, const float* __restrict__ h0) {
    __shared__ float ihs[SEQ * REC];
    __shared__ float hsm[2][REC];
    int b = blockIdx.x, lane = threadIdx.x;

#pragma unroll 8
    for (int i = lane; i < SEQ * REC; i += 32)
        ihs[i] = g_ih[b * (SEQ * REC) + i];

    int j = lane >> 1, half = lane & 1;
    float Wr[8];
#pragma unroll
    for (int k = 0; k < 8; k++) Wr[k] = W[j * REC + half * 8 + k];

    if (lane < REC) hsm[0][lane] = h0[lane];
    __syncwarp();

    int cur = 0;
    __half* hrow = &g_h16[b * REC];
    for (int t = 0; t < SEQ; t++) {
        if (!half) hrow[j] = __float2half_rn(hsm[cur][j]);
        if (t == SEQ - 1) break;
        hrow += BATCH * REC;

        const float* hp = &hsm[cur][half * 8];
        float a0 = Wr[0]*hp[0], a1 = Wr[1]*hp[1];
        a0 = fmaf(Wr[2], hp[2], a0); a1 = fmaf(Wr[3], hp[3], a1);
        a0 = fmaf(Wr[4], hp[4], a0); a1 = fmaf(Wr[5], hp[5], a1);
        a0 = fmaf(Wr[6], hp[6], a0); a1 = fmaf(Wr[7], hp[7], a1);
        float acc = a0 + a1;
        acc += __shfl_xor_sync(0xffffffffu, acc, 1);
        float z = fmaf(acc, 2.0f * LOG2E, ihs[t * REC + j]);
        float e = ex2f(z);
        float hn = fmaf(-2.0f, rcpf(1.0f + e), 1.0f);
        if (!half) hsm[cur ^ 1][j] = hn;
        __syncwarp();
        cur ^= 1;
    }
}

// ---- pass1: f16-accum MMA, packed exp, sum into g_sums ----
__global__ void __launch_bounds__(256) k_p1(const float* __restrict__ V) {
    __shared__ __align__(16) char smA[MCH * ASTRIDE];
    __shared__ float ssum[MCH];
    int tid = threadIdx.x, wid = tid >> 5, lane = tid & 31;
    int mbase = blockIdx.y * MCH;
    int w0 = blockIdx.x * 128 + wid * 16;

    for (int r = tid; r < MCH; r += 256) {
        const uint4* s = (const uint4*)&g_h16[(size_t)(mbase + r) * REC];
        uint4 x0 = s[0], x1 = s[1];
        *(uint4*)(smA + r * ASTRIDE)      = x0;
        *(uint4*)(smA + r * ASTRIDE + 16) = x1;
    }
    for (int r = tid; r < MCH; r += 256) ssum[r] = 0.f;

    uint32_t B[2][2];
    load_bfrag(B, V, w0, lane);

    uint32_t abase = su32(smA) + (lane & 15) * ASTRIDE + (lane >> 4) * 16;
    __syncthreads();

    int q = lane & 3, g = lane >> 2;
    for (int i = 0; i < NT; i++) {
        int mt = (i + wid * 4) & (NT - 1);
        uint32_t a[4];
        ldsmx4(a, abase + mt * (16 * ASTRIDE));
        uint32_t c[2] = {0, 0}, d[2] = {0, 0};
        mma16h(c, a, B[0][0], B[0][1]);
        mma16h(d, a, B[1][0], B[1][1]);
        // packed exp: 4 MUFU covers 8 logits
        __half2 ec0 = h2ex2(*(__half2*)&c[0]);
        __half2 ed0 = h2ex2(*(__half2*)&d[0]);
        __half2 ec1 = h2ex2(*(__half2*)&c[1]);
        __half2 ed1 = h2ex2(*(__half2*)&d[1]);
        __half2 s0 = __hadd2(ec0, ed0);   // row g
        __half2 s1 = __hadd2(ec1, ed1);   // row g+8
        uint32_t u0 = *(uint32_t*)&s0, u1 = *(uint32_t*)&s1;
        uint32_t t0 = __shfl_xor_sync(0xffffffffu, u0, 1);
        uint32_t t1 = __shfl_xor_sync(0xffffffffu, u1, 1);
        s0 = __hadd2(*(__half2*)&u0, *(__half2*)&t0);
        s1 = __hadd2(*(__half2*)&u1, *(__half2*)&t1);
        u0 = *(uint32_t*)&s0; u1 = *(uint32_t*)&s1;
        t0 = __shfl_xor_sync(0xffffffffu, u0, 2);
        t1 = __shfl_xor_sync(0xffffffffu, u1, 2);
        s0 = __hadd2(*(__half2*)&u0, *(__half2*)&t0);
        s1 = __hadd2(*(__half2*)&u1, *(__half2*)&t1);
        if (q == 0) {
            float2 f0 = __half22float2(s0);
            float2 f1 = __half22float2(s1);
            atomicAdd(&ssum[mt * 16 + g],     f0.x + f0.y);
            atomicAdd(&ssum[mt * 16 + g + 8], f1.x + f1.y);
        }
    }
    __syncthreads();
    for (int r = tid; r < MCH; r += 256) atomicAdd(&g_sums[mbase + r], ssum[r]);
}

// ---- pass2: f32-accum MMA, in-CTA lse, coalesced STG.128 ----
__global__ void __launch_bounds__(256) k_p2(const float* __restrict__ V, float* __restrict__ out) {
    __shared__ __align__(16) char smA[MCH * ASTRIDE];
    __shared__ float ms[MCH];
    int tid = threadIdx.x, wid = tid >> 5, lane = tid & 31;
    int mbase = blockIdx.y * MCH;
    int w0 = blockIdx.x * 128 + wid * 16;

    for (int r = tid; r < MCH; r += 256) {
        const uint4* s = (const uint4*)&g_h16[(size_t)(mbase + r) * REC];
        uint4 x0 = s[0], x1 = s[1];
        *(uint4*)(smA + r * ASTRIDE)      = x0;
        *(uint4*)(smA + r * ASTRIDE + 16) = x1;
    }
    for (int r = tid; r < MCH; r += 256)
        ms[r] = lg2f(g_sums[mbase + r]) * LN2;   // lse in nat units

    uint32_t B[2][2];
    load_bfrag(B, V, w0, lane);

    uint32_t abase = su32(smA) + (lane & 15) * ASTRIDE + (lane >> 4) * 16;
    __syncthreads();

    int q = lane & 3, g = lane >> 2;
    int vcol = w0 + 4 * q;
    for (int i = 0; i < NT; i++) {
        int mt = (i + wid * 4) & (NT - 1);
        uint32_t a[4];
        ldsmx4(a, abase + mt * (16 * ASTRIDE));
        float c[4] = {0,0,0,0}, d[4] = {0,0,0,0};
        mma16f(c, a, B[0][0], B[0][1]);
        mma16f(d, a, B[1][0], B[1][1]);
        int r0 = mt * 16 + g;
        float m0 = ms[r0], m1 = ms[r0 + 8];
        float4 o0, o1;
        o0.x = fmaf(c[0], LN2, -m0); o0.y = fmaf(c[1], LN2, -m0);
        o0.z = fmaf(d[0], LN2, -m0); o0.w = fmaf(d[1], LN2, -m0);
        o1.x = fmaf(c[2], LN2, -m1); o1.y = fmaf(c[3], LN2, -m1);
        o1.z = fmaf(d[2], LN2, -m1); o1.w = fmaf(d[3], LN2, -m1);
        *(float4*)(out + (size_t)(mbase + r0) * VOCAB + vcol)     = o0;
        *(float4*)(out + (size_t)(mbase + r0 + 8) * VOCAB + vcol) = o1;
    }
}

extern "C" void kernel_launch(void* const* d_in, const int* in_sizes, int n_in,
                              void* d_out, int out_size) {
    const int*   input_batch = (const int*)  d_in[0];
    const float* embedding   = (const float*)d_in[1];
    const float* U           = (const float*)d_in[2];
    const float* W           = (const float*)d_in[3];
    const float* V           = (const float*)d_in[4];
    const float* b1          = (const float*)d_in[5];
    const float* b2          = (const float*)d_in[6];
    const float* h0          = (const float*)d_in[7];
    float* out = (float*)d_out;

    k_ih  <<<(NROWS * REC) / 256, 256>>>(input_batch, embedding, U, b1, b2);
    k_rnn <<<BATCH, 32>>>(W, h0);
    k_p1  <<<dim3(GX, GY), 256>>>(V);
    k_p2  <<<dim3(GX, GY), 256>>>(V, out);
}